// round 6
// baseline (speedup 1.0000x reference)
#include <cuda_runtime.h>
#include <cstdint>

#define K_DIM   5120
#define E_DIM   5120
#define N_NODES 27
#define HD      1280
#define TOT_T16 20          // total B tiles (each = 16 k16 = 256 k)

// ---- scratch (device globals; no allocations allowed) ----
__device__ float    g_qkvT[15360 * 28];    // qkv transposed [3E][28]
__device__ float    g_o[N_NODES * E_DIM];  // attention output [27][5120]
__device__ float    g_colrow[54];
__device__ float    g_scores[4 * 729];
__device__ float    g_attn[4 * 729];
// B operand in MMA-fragment order: [k16 (320)][frag (8 = nt*2+reg)][lane (32)]
__device__ uint32_t g_bhi[320 * 256];
__device__ uint32_t g_blo[320 * 256];

static __device__ __forceinline__ float hw_from(const int* lh) {
    int iv = *lh;
    float f = (iv > 0 && iv < 100000000) ? (float)iv : __int_as_float(iv);
    return fminf(fmaxf(f * 0.001f, 0.1f), 1.0f);
}

static __device__ __forceinline__ uint32_t smem_u32(const void* p) {
    uint32_t a;
    asm("{ .reg .u64 t; cvta.to.shared.u64 t, %1; cvt.u32.u64 %0, t; }" : "=r"(a) : "l"(p));
    return a;
}

// Split f32 pair -> bf16x2 hi (exact truncation) + bf16x2 lo (rounded remainder).
static __device__ __forceinline__ void split_pack(float f0, float f1,
                                                  uint32_t& hi, uint32_t& lo) {
    uint32_t u0 = __float_as_uint(f0), u1 = __float_as_uint(f1);
    asm("prmt.b32 %0, %1, %2, 0x7632;" : "=r"(hi) : "r"(u0), "r"(u1));
    float l0 = f0 - __uint_as_float(u0 & 0xFFFF0000u);
    float l1 = f1 - __uint_as_float(u1 & 0xFFFF0000u);
    asm("cvt.rn.bf16x2.f32 %0, %1, %2;" : "=r"(lo) : "f"(l1), "f"(l0));
}

#define MMA_BF16(d, a, b0, b1)                                                  \
    asm volatile(                                                               \
        "mma.sync.aligned.m16n8k16.row.col.f32.bf16.bf16.f32 "                  \
        "{%0,%1,%2,%3}, {%4,%5,%6,%7}, {%8,%9}, {%0,%1,%2,%3};"                 \
        : "+f"((d)[0]), "+f"((d)[1]), "+f"((d)[2]), "+f"((d)[3])                \
        : "r"((a)[0]), "r"((a)[1]), "r"((a)[2]), "r"((a)[3]),                   \
          "r"(b0), "r"(b1))

#define CP_ASYNC16(saddr, gptr)                                                 \
    asm volatile("cp.async.cg.shared.global [%0], [%1], 16;"                    \
                 :: "r"(saddr), "l"(gptr))
#define CP_COMMIT()  asm volatile("cp.async.commit_group;" ::: "memory")
#define CP_WAIT0()   asm volatile("cp.async.wait_group 0;" ::: "memory")
#define CP_WAIT1()   asm volatile("cp.async.wait_group 1;" ::: "memory")

// =====================================================================
// Fragment prep for X (27 x 5120): b-frag for m16n8k16:
//   reg0 = X[n = nt*8 + lane>>2][k0, k0+1], reg1 = [k0+8, k0+9],
//   k0 = k16*16 + 2*(lane&3).  4 k16 per thread for ILP.
// =====================================================================
static __device__ __forceinline__ void prep_body(const float* __restrict__ src, int t4)
{
    int lane = t4 & 31;
    int f    = (t4 >> 5) & 7;
    int k16b = (t4 >> 8) * 4;
    int reg  = f & 1;
    int nt   = f >> 1;
    int n    = nt * 8 + (lane >> 2);
    const bool ok = (n < N_NODES);
    const float* row = src + (size_t)n * K_DIM;
    float f0[4], f1[4];
    #pragma unroll
    for (int u = 0; u < 4; u++) {
        int k0 = (k16b + u) * 16 + reg * 8 + 2 * (lane & 3);
        f0[u] = ok ? row[k0]     : 0.0f;
        f1[u] = ok ? row[k0 + 1] : 0.0f;
    }
    #pragma unroll
    for (int u = 0; u < 4; u++) {
        uint32_t hi, lo;
        split_pack(f0[u], f1[u], hi, lo);
        int idx = (k16b + u) * 256 + f * 32 + lane;
        g_bhi[idx] = hi;
        g_blo[idx] = lo;
    }
}

__global__ __launch_bounds__(256)
void prep2_kernel()  // g_o -> fragments (after attention)
{
    prep_body(g_o, blockIdx.x * 256 + threadIdx.x);
}

// Fused: prep(node) + bias seeding + score zeroing.
//   blocks [0,80): prep node; [80, ...): init outputs
__global__ __launch_bounds__(256)
void pre_kernel(const float* __restrict__ node, const float* __restrict__ inb,
                const float* __restrict__ outb, const int* __restrict__ lh,
                float* __restrict__ out)
{
    if (blockIdx.x < 80) {
        prep_body(node, blockIdx.x * 256 + threadIdx.x);
        return;
    }
    const int t = (blockIdx.x - 80) * 256 + threadIdx.x;
    if (t < 15360 * 27) {
        int m = t / 27, n = t - m * 27;
        g_qkvT[m * 28 + n] = inb[m];
    } else if (t < 15360 * 27 + 27 * 5120) {
        int t2 = t - 15360 * 27;
        int m = t2 % 5120;
        out[t2] = outb[m] * hw_from(lh);
    } else if (t < 15360 * 27 + 27 * 5120 + 4 * 729) {
        g_scores[t - (15360 * 27 + 27 * 5120)] = 0.0f;
    }
}

// =====================================================================
// Legacy-HMMA split-K GEMM:  D[m][n] = sum_k W[m][k] * X[n][k]
//   CTA: 128 threads, 4 warps x 32 rows = 128 W-rows.
//   grid.x = M/128, grid.y = K splits; split y covers tiles
//   [y*spl_t, min((y+1)*spl_t, TOT_T16)).
//   B double-buffered via cp.async; A 2-deep register prefetch.
// =====================================================================
__global__ __launch_bounds__(128, 3)
void gemm_hmma(const float* __restrict__ W, float* __restrict__ dst,
               int mode, int spl_t, const int* __restrict__ lh)
{
    extern __shared__ uint32_t sB[];   // [2 buf][hi/lo 4096 each] = 64KB

    const int tid  = threadIdx.x;
    const int lane = tid & 31;
    const int wid  = tid >> 5;
    const int mbase = blockIdx.x * 128 + wid * 32;
    const int kt0   = blockIdx.y * spl_t;
    const int ntile = min(spl_t, TOT_T16 - kt0);
    const int nk16  = ntile * 16;
    const int r  = lane >> 2;
    const int t2 = (lane & 3) * 2;
    const uint32_t sbase = smem_u32(sB);

    const float* wp = W + (size_t)(mbase + r) * K_DIM + (size_t)kt0 * 256 + t2;

    // ---- B tile async copy: 32KB per tile (16KB hi + 16KB lo) ----
    auto issueB = [&](int tile, int buf) {
        const char* srcH = (const char*)(g_bhi + (size_t)(kt0 + tile) * 16 * 256);
        const char* srcL = (const char*)(g_blo + (size_t)(kt0 + tile) * 16 * 256);
        uint32_t dH = sbase + buf * 32768;
        uint32_t dL = dH + 16384;
        #pragma unroll
        for (int j = 0; j < 8; j++) {
            int ch = (tid + j * 128) * 16;
            CP_ASYNC16(dH + ch, srcH + ch);
            CP_ASYNC16(dL + ch, srcL + ch);
        }
        CP_COMMIT();
    };

    float acc[2][4][4];
    #pragma unroll
    for (int mf = 0; mf < 2; mf++)
        #pragma unroll
        for (int nt = 0; nt < 4; nt++)
            #pragma unroll
            for (int q = 0; q < 4; q++) acc[mf][nt][q] = 0.0f;

    // A stage: [buf][mf*4 + kc*2 + rr]
    float2 stage[2][8];
    auto ldA = [&](int i, int buf) {
        #pragma unroll
        for (int mf = 0; mf < 2; mf++)
            #pragma unroll
            for (int kc = 0; kc < 2; kc++)
                #pragma unroll
                for (int rr = 0; rr < 2; rr++)
                    stage[buf][mf * 4 + kc * 2 + rr] =
                        *(const float2*)(wp + (size_t)(mf * 16 + rr * 8) * K_DIM
                                         + (size_t)i * 16 + kc * 8);
    };

    // prologue
    issueB(0, 0);
    if (ntile > 1) issueB(1, 1);
    ldA(0, 0);
    if (nk16 > 1) ldA(1, 1);
    if (ntile > 1) CP_WAIT1(); else CP_WAIT0();

    #pragma unroll 1
    for (int tile = 0; tile < ntile; tile++) {
        __syncthreads();   // B buf (tile&1) arrived & all threads past prior use
        const uint32_t bH = sbase + (tile & 1) * 32768;
        const uint32_t bL = bH + 16384;

        #pragma unroll 1
        for (int c = 0; c < 16; c++) {
            const int i = tile * 16 + c;
            // convert staged A
            uint32_t ahi[2][4], alo[2][4];
            #pragma unroll
            for (int q = 0; q < 8; q++)
                split_pack(stage[i & 1][q].x, stage[i & 1][q].y,
                           ahi[q >> 2][q & 3], alo[q >> 2][q & 3]);
            // prefetch A for i+2 into freed buffer
            if (i + 2 < nk16) ldA(i + 2, i & 1);

            // B fragments (lane-consecutive, conflict-free)
            uint32_t bh[4][2], bl[4][2];
            #pragma unroll
            for (int nt = 0; nt < 4; nt++) {
                uint32_t o0 = ((c * 8 + nt * 2 + 0) * 32 + lane) * 4;
                uint32_t o1 = ((c * 8 + nt * 2 + 1) * 32 + lane) * 4;
                asm volatile("ld.shared.b32 %0, [%1];" : "=r"(bh[nt][0]) : "r"(bH + o0));
                asm volatile("ld.shared.b32 %0, [%1];" : "=r"(bh[nt][1]) : "r"(bH + o1));
                asm volatile("ld.shared.b32 %0, [%1];" : "=r"(bl[nt][0]) : "r"(bL + o0));
                asm volatile("ld.shared.b32 %0, [%1];" : "=r"(bl[nt][1]) : "r"(bL + o1));
            }

            #pragma unroll
            for (int mf = 0; mf < 2; mf++)
                #pragma unroll
                for (int nt = 0; nt < 4; nt++) {
                    MMA_BF16(acc[mf][nt], ahi[mf], bh[nt][0], bh[nt][1]);
                    MMA_BF16(acc[mf][nt], ahi[mf], bl[nt][0], bl[nt][1]);
                    MMA_BF16(acc[mf][nt], alo[mf], bh[nt][0], bh[nt][1]);
                }
        }

        __syncthreads();   // all warps done with this B buf
        if (tile + 2 < ntile) { issueB(tile + 2, tile & 1); CP_WAIT1(); }
        else CP_WAIT0();
    }

    // epilogue: d0=(m0,n0) d1=(m0,n0+1) d2=(m0+8,n0) d3=(m0+8,n0+1)
    if (mode == 0) {
        #pragma unroll
        for (int mf = 0; mf < 2; mf++) {
            int m0 = mbase + mf * 16 + r;
            #pragma unroll
            for (int nt = 0; nt < 4; nt++) {
                int n0 = nt * 8 + t2;
                if (n0 < N_NODES)     atomicAdd(&g_qkvT[m0 * 28 + n0],           acc[mf][nt][0]);
                if (n0 + 1 < N_NODES) atomicAdd(&g_qkvT[m0 * 28 + n0 + 1],       acc[mf][nt][1]);
                if (n0 < N_NODES)     atomicAdd(&g_qkvT[(m0 + 8) * 28 + n0],     acc[mf][nt][2]);
                if (n0 + 1 < N_NODES) atomicAdd(&g_qkvT[(m0 + 8) * 28 + n0 + 1], acc[mf][nt][3]);
            }
        }
    } else {
        const float hw = hw_from(lh);
        #pragma unroll
        for (int mf = 0; mf < 2; mf++) {
            int m0 = mbase + mf * 16 + r;
            #pragma unroll
            for (int nt = 0; nt < 4; nt++) {
                int n0 = nt * 8 + t2;
                if (n0 < N_NODES)     atomicAdd(&dst[(size_t)n0 * E_DIM + m0],           acc[mf][nt][0] * hw);
                if (n0 + 1 < N_NODES) atomicAdd(&dst[(size_t)(n0 + 1) * E_DIM + m0],     acc[mf][nt][1] * hw);
                if (n0 < N_NODES)     atomicAdd(&dst[(size_t)n0 * E_DIM + m0 + 8],       acc[mf][nt][2] * hw);
                if (n0 + 1 < N_NODES) atomicAdd(&dst[(size_t)(n0 + 1) * E_DIM + m0 + 8], acc[mf][nt][3] * hw);
            }
        }
    }
}

// =====================================================================
// Attention
// =====================================================================
__global__ __launch_bounds__(256)
void attn_scores()
{
    const int ct = blockIdx.x;   // 0..9 (128-channel tile)
    const int h  = blockIdx.y;   // 0..3
    __shared__ float sq[128 * 29];
    __shared__ float sk[128 * 29];
    const int tid = threadIdx.x;

    const float* qb = g_qkvT + (size_t)(h * HD + ct * 128) * 28;
    const float* kb = g_qkvT + (size_t)(E_DIM + h * HD + ct * 128) * 28;
    for (int idx = tid; idx < 128 * 28; idx += 256) {
        int c = idx / 28, r = idx - c * 28;
        sq[c * 29 + r] = qb[idx];
        sk[c * 29 + r] = kb[idx];
    }
    __syncthreads();

    for (int t = tid; t < 729; t += 256) {
        int i = t / 27, j = t - i * 27;
        float s = 0.0f;
        #pragma unroll 8
        for (int c = 0; c < 128; c++)
            s += sq[c * 29 + i] * sk[c * 29 + j];
        atomicAdd(&g_scores[h * 729 + t], s);
    }
}

// softmax (threads <108) + causal adjacency output (all threads)
__global__ __launch_bounds__(256)
void attn_softmax_adj(const float* __restrict__ gb, float* __restrict__ out)
{
    const int t = threadIdx.x;
    if (t < 108) {
        const int h = t / 27, i = t - h * 27;
        const float scale = rsqrtf((float)HD);
        const float* sc = g_scores + h * 729 + i * 27;
        float mx = -1e30f;
        #pragma unroll
        for (int j = 0; j < 27; j++) mx = fmaxf(mx, sc[j] * scale);
        float e[27], sum = 0.0f;
        #pragma unroll
        for (int j = 0; j < 27; j++) { e[j] = expf(sc[j] * scale - mx); sum += e[j]; }
        const float inv = 1.0f / sum;
        float* at = g_attn + h * 729 + i * 27;
        #pragma unroll
        for (int j = 0; j < 27; j++) at[j] = e[j] * inv;
    }
    for (int idx = t; idx < 729; idx += 256) {
        int i = idx / 27, j = idx - i * 27;
        float v = 0.0f;
        if (i != j)
            v = 1.0f / (1.0f + expf(-(g_colrow[i] + g_colrow[27 + j] + gb[0])));
        out[N_NODES * E_DIM + idx] = v;
    }
}

__global__ __launch_bounds__(256)
void attn_out()
{
    const int ct = blockIdx.x;
    const int h  = blockIdx.y;
    __shared__ float sv[128 * 29];
    __shared__ float sa[729];
    const int tid = threadIdx.x;

    const float* vb = g_qkvT + (size_t)(2 * E_DIM + h * HD + ct * 128) * 28;
    for (int idx = tid; idx < 128 * 28; idx += 256) {
        int c = idx / 28, r = idx - c * 28;
        sv[c * 29 + r] = vb[idx];
    }
    for (int idx = tid; idx < 729; idx += 256) sa[idx] = g_attn[h * 729 + idx];
    __syncthreads();

    for (int f = tid; f < 27 * 128; f += 256) {
        int c = f & 127, i = f >> 7;
        float o = 0.0f;
        #pragma unroll
        for (int j = 0; j < 27; j++) o += sa[i * 27 + j] * sv[c * 29 + j];
        g_o[(size_t)i * E_DIM + h * HD + ct * 128 + c] = o;
    }
}

// =====================================================================
// Granger dots
// =====================================================================
__global__ __launch_bounds__(256)
void granger_dots(const float* __restrict__ node, const float* __restrict__ hist,
                  const float* __restrict__ gw)
{
    const int b = blockIdx.x;  // 0..53
    const float* x  = (b < 27) ? node + (size_t)b * E_DIM : hist + (size_t)(b - 27) * E_DIM;
    const float* wv = (b < 27) ? gw + E_DIM : gw;
    const int tid = threadIdx.x;

    float s = 0.0f;
    for (int k = tid; k < E_DIM; k += 256) s += x[k] * wv[k];

    __shared__ float sred[8];
    #pragma unroll
    for (int off = 16; off; off >>= 1) s += __shfl_xor_sync(0xffffffffu, s, off);
    if ((tid & 31) == 0) sred[tid >> 5] = s;
    __syncthreads();
    if (tid < 8) {
        s = sred[tid];
        #pragma unroll
        for (int off = 4; off; off >>= 1) s += __shfl_xor_sync(0x000000ffu, s, off);
        if (tid == 0) g_colrow[b] = s;
    }
}

// =====================================================================
extern "C" void kernel_launch(void* const* d_in, const int* in_sizes, int n_in,
                              void* d_out, int out_size)
{
    const float* node = (const float*)d_in[0];
    const float* hist = (const float*)d_in[1];
    const float* gw   = (const float*)d_in[2];
    const float* gb   = (const float*)d_in[3];
    const float* inw  = (const float*)d_in[4];
    const float* inb  = (const float*)d_in[5];
    const float* outw = (const float*)d_in[6];
    const float* outb = (const float*)d_in[7];
    const int*   lh   = (const int*)d_in[8];
    float* out = (float*)d_out;

    cudaFuncSetAttribute(gemm_hmma, cudaFuncAttributeMaxDynamicSharedMemorySize, 65536);

    granger_dots<<<54, 256>>>(node, hist, gw);

    const int init_elems = 15360 * 27 + 27 * 5120 + 4 * 729;
    pre_kernel<<<80 + (init_elems + 255) / 256, 256>>>(node, inb, outb, lh, out);

    // qkv += x @ in_proj_w^T : 120 M-tiles x 3 K-splits (tiles 7/7/6)
    gemm_hmma<<<dim3(120, 3), 128, 65536>>>(inw, nullptr, 0, 7, lh);

    attn_scores<<<dim3(10, 4), 256>>>();
    attn_softmax_adj<<<1, 256>>>(gb, out);
    attn_out<<<dim3(10, 4), 256>>>();

    prep2_kernel<<<80, 256>>>();

    // out += (o @ out_proj_w^T) * hw : 40 M-tiles x 10 K-splits (2 tiles each)
    gemm_hmma<<<dim3(40, 10), 128, 65536>>>(outw, out, 1, 2, lh);
}

// round 7
// speedup vs baseline: 1.3995x; 1.3995x over previous
#include <cuda_runtime.h>
#include <cstdint>

#define K_DIM   5120
#define E_DIM   5120
#define N_NODES 27
#define HD      1280

// ---- scratch (device globals; no allocations allowed) ----
__device__ float    g_qkvT[15360 * 28];    // qkv transposed [3E][28]
__device__ float    g_colrow[54];
__device__ float    g_scores[4 * 729];
__device__ float    g_attn[4 * 729];
__device__ int      g_cnt;
// B operand in MMA-fragment order: [k16 (320)][frag (8 = nt*2+reg)][lane (32)]
__device__ uint32_t g_bhi[320 * 256];
__device__ uint32_t g_blo[320 * 256];

static __device__ __forceinline__ float hw_from(const int* lh) {
    int iv = *lh;
    float f = (iv > 0 && iv < 100000000) ? (float)iv : __int_as_float(iv);
    return fminf(fmaxf(f * 0.001f, 0.1f), 1.0f);
}

// Split f32 pair -> bf16x2 hi (exact truncation) + bf16x2 lo (rounded remainder).
static __device__ __forceinline__ void split_pack(float f0, float f1,
                                                  uint32_t& hi, uint32_t& lo) {
    uint32_t u0 = __float_as_uint(f0), u1 = __float_as_uint(f1);
    asm("prmt.b32 %0, %1, %2, 0x7632;" : "=r"(hi) : "r"(u0), "r"(u1));
    float l0 = f0 - __uint_as_float(u0 & 0xFFFF0000u);
    float l1 = f1 - __uint_as_float(u1 & 0xFFFF0000u);
    asm("cvt.rn.bf16x2.f32 %0, %1, %2;" : "=r"(lo) : "f"(l1), "f"(l0));
}

#define MMA_BF16(d, a, b0, b1)                                                  \
    asm volatile(                                                               \
        "mma.sync.aligned.m16n8k16.row.col.f32.bf16.bf16.f32 "                  \
        "{%0,%1,%2,%3}, {%4,%5,%6,%7}, {%8,%9}, {%0,%1,%2,%3};"                 \
        : "+f"((d)[0]), "+f"((d)[1]), "+f"((d)[2]), "+f"((d)[3])                \
        : "r"((a)[0]), "r"((a)[1]), "r"((a)[2]), "r"((a)[3]),                   \
          "r"(b0), "r"(b1))

// =====================================================================
// Fragment prep for X (27 x 5120): b-frag for m16n8k16:
//   reg0 = X[n = nt*8 + lane>>2][k0, k0+1], reg1 = [k0+8, k0+9],
//   k0 = k16*16 + 2*(lane&3).  4 k16 per thread for ILP.
// =====================================================================
static __device__ __forceinline__ void prep_body(const float* __restrict__ src, int t4)
{
    int lane = t4 & 31;
    int f    = (t4 >> 5) & 7;
    int k16b = (t4 >> 8) * 4;
    int reg  = f & 1;
    int nt   = f >> 1;
    int n    = nt * 8 + (lane >> 2);
    const bool ok = (n < N_NODES);
    const float* row = src + (size_t)n * K_DIM;
    float f0[4], f1[4];
    #pragma unroll
    for (int u = 0; u < 4; u++) {
        int k0 = (k16b + u) * 16 + reg * 8 + 2 * (lane & 3);
        f0[u] = ok ? row[k0]     : 0.0f;
        f1[u] = ok ? row[k0 + 1] : 0.0f;
    }
    #pragma unroll
    for (int u = 0; u < 4; u++) {
        uint32_t hi, lo;
        split_pack(f0[u], f1[u], hi, lo);
        int idx = (k16b + u) * 256 + f * 32 + lane;
        g_bhi[idx] = hi;
        g_blo[idx] = lo;
    }
}

// =====================================================================
// pre: blocks [0,80) prep node frags | [80,134) granger dots | rest init
// =====================================================================
__global__ __launch_bounds__(256)
void pre_kernel(const float* __restrict__ node, const float* __restrict__ hist,
                const float* __restrict__ gw, const float* __restrict__ inb,
                const float* __restrict__ outb, const int* __restrict__ lh,
                float* __restrict__ out)
{
    const int bx = blockIdx.x;
    const int tid = threadIdx.x;

    if (bx < 80) { prep_body(node, bx * 256 + tid); return; }

    if (bx < 134) {   // granger dot b (0..53)
        const int b = bx - 80;
        const float* x  = (b < 27) ? node + (size_t)b * E_DIM : hist + (size_t)(b - 27) * E_DIM;
        const float* wv = (b < 27) ? gw + E_DIM : gw;
        float s = 0.0f;
        for (int k = tid; k < E_DIM; k += 256) s += x[k] * wv[k];
        __shared__ float sred[8];
        #pragma unroll
        for (int off = 16; off; off >>= 1) s += __shfl_xor_sync(0xffffffffu, s, off);
        if ((tid & 31) == 0) sred[tid >> 5] = s;
        __syncthreads();
        if (tid < 8) {
            s = sred[tid];
            #pragma unroll
            for (int off = 4; off; off >>= 1) s += __shfl_xor_sync(0x000000ffu, s, off);
            if (tid == 0) g_colrow[b] = s;
        }
        return;
    }

    int t = (bx - 134) * 256 + tid;
    if (t < 15360 * 27) {                       // qkvT bias seed
        int m = t / 27, n = t - m * 27;
        g_qkvT[m * 28 + n] = inb[m];
    } else if (t < 15360 * 27 + 27 * 5120) {    // out bias*hw seed
        int t2 = t - 15360 * 27;
        out[t2] = outb[t2 % 5120] * hw_from(lh);
    } else if (t < 15360 * 27 + 27 * 5120 + 4 * 729) {
        g_scores[t - (15360 * 27 + 27 * 5120)] = 0.0f;
    } else if (t == 15360 * 27 + 27 * 5120 + 4 * 729) {
        g_cnt = 0;
    }
}

// =====================================================================
// Barrier-free HMMA split-K GEMM:  D[m][n] = sum_k W[m][k] * X[n][k]
//   128 thr = 4 warps x 32 rows.  A: dist-2 reg prefetch (DRAM).
//   B: dist-1 reg prefetch straight from global (L2-resident frags).
//   Compile-time buffer indices via template -> no local-memory demotion.
// =====================================================================
template<int BUF>
static __device__ __forceinline__ void gstep(
    int& i, int nk16, int k16_0, const float* __restrict__ wp, int lane,
    float2 (&Ast)[2][8], uint32_t (&Bh)[2][8], uint32_t (&Bl)[2][8],
    float (&acc)[2][4][4])
{
    constexpr int NBUF = BUF ^ 1;
    // B prefetch for i+1 (L2 hit, one full step of slack)
    if (i + 1 < nk16) {
        const int kb = (k16_0 + i + 1) * 256 + lane;
        #pragma unroll
        for (int f = 0; f < 8; f++) {
            Bh[NBUF][f] = g_bhi[kb + f * 32];
            Bl[NBUF][f] = g_blo[kb + f * 32];
        }
    }
    // convert staged A (waits on loads issued at i-2)
    uint32_t ahi[2][4], alo[2][4];
    #pragma unroll
    for (int q = 0; q < 8; q++)
        split_pack(Ast[BUF][q].x, Ast[BUF][q].y, ahi[q >> 2][q & 3], alo[q >> 2][q & 3]);
    // A prefetch for i+2 into freed buffer
    if (i + 2 < nk16) {
        #pragma unroll
        for (int mf = 0; mf < 2; mf++)
            #pragma unroll
            for (int kc = 0; kc < 2; kc++)
                #pragma unroll
                for (int rr = 0; rr < 2; rr++)
                    Ast[BUF][mf * 4 + kc * 2 + rr] =
                        *(const float2*)(wp + (size_t)(mf * 16 + rr * 8) * K_DIM
                                         + (size_t)(i + 2) * 16 + kc * 8);
    }
    #pragma unroll
    for (int mf = 0; mf < 2; mf++)
        #pragma unroll
        for (int nt = 0; nt < 4; nt++) {
            MMA_BF16(acc[mf][nt], ahi[mf], Bh[BUF][nt * 2], Bh[BUF][nt * 2 + 1]);
            MMA_BF16(acc[mf][nt], ahi[mf], Bl[BUF][nt * 2], Bl[BUF][nt * 2 + 1]);
            MMA_BF16(acc[mf][nt], alo[mf], Bh[BUF][nt * 2], Bh[BUF][nt * 2 + 1]);
        }
    i++;
}

__global__ __launch_bounds__(128, 3)
void gemm_hmma(const float* __restrict__ W, float* __restrict__ dst,
               int mode, int spl16, const int* __restrict__ lh)
{
    const int tid  = threadIdx.x;
    const int lane = tid & 31;
    const int wid  = tid >> 5;
    const int mbase = blockIdx.x * 128 + wid * 32;
    const int k16_0 = blockIdx.y * spl16;
    const int nk16  = min(spl16, 320 - k16_0);
    const int r  = lane >> 2;
    const int t2 = (lane & 3) * 2;

    const float* wp = W + (size_t)(mbase + r) * K_DIM + (size_t)k16_0 * 16 + t2;

    float acc[2][4][4];
    #pragma unroll
    for (int mf = 0; mf < 2; mf++)
        #pragma unroll
        for (int nt = 0; nt < 4; nt++)
            #pragma unroll
            for (int q = 0; q < 4; q++) acc[mf][nt][q] = 0.0f;

    float2   Ast[2][8];
    uint32_t Bh[2][8], Bl[2][8];

    // prologue: A(0)->buf0, A(1)->buf1, B(0)->buf0
    #pragma unroll
    for (int mf = 0; mf < 2; mf++)
        #pragma unroll
        for (int kc = 0; kc < 2; kc++)
            #pragma unroll
            for (int rr = 0; rr < 2; rr++)
                Ast[0][mf * 4 + kc * 2 + rr] =
                    *(const float2*)(wp + (size_t)(mf * 16 + rr * 8) * K_DIM + kc * 8);
    if (nk16 > 1) {
        #pragma unroll
        for (int mf = 0; mf < 2; mf++)
            #pragma unroll
            for (int kc = 0; kc < 2; kc++)
                #pragma unroll
                for (int rr = 0; rr < 2; rr++)
                    Ast[1][mf * 4 + kc * 2 + rr] =
                        *(const float2*)(wp + (size_t)(mf * 16 + rr * 8) * K_DIM + 16 + kc * 8);
    }
    {
        const int kb = k16_0 * 256 + lane;
        #pragma unroll
        for (int f = 0; f < 8; f++) {
            Bh[0][f] = g_bhi[kb + f * 32];
            Bl[0][f] = g_blo[kb + f * 32];
        }
    }

    int i = 0;
    while (true) {
        gstep<0>(i, nk16, k16_0, wp, lane, Ast, Bh, Bl, acc);
        if (i >= nk16) break;
        gstep<1>(i, nk16, k16_0, wp, lane, Ast, Bh, Bl, acc);
        if (i >= nk16) break;
    }

    // epilogue: d0=(m0,n0) d1=(m0,n0+1) d2=(m0+8,n0) d3=(m0+8,n0+1)
    if (mode == 0) {
        #pragma unroll
        for (int mf = 0; mf < 2; mf++) {
            int m0 = mbase + mf * 16 + r;
            #pragma unroll
            for (int nt = 0; nt < 4; nt++) {
                int n0 = nt * 8 + t2;
                if (n0 < N_NODES)     atomicAdd(&g_qkvT[m0 * 28 + n0],           acc[mf][nt][0]);
                if (n0 + 1 < N_NODES) atomicAdd(&g_qkvT[m0 * 28 + n0 + 1],       acc[mf][nt][1]);
                if (n0 < N_NODES)     atomicAdd(&g_qkvT[(m0 + 8) * 28 + n0],     acc[mf][nt][2]);
                if (n0 + 1 < N_NODES) atomicAdd(&g_qkvT[(m0 + 8) * 28 + n0 + 1], acc[mf][nt][3]);
            }
        }
    } else {
        const float hw = hw_from(lh);
        #pragma unroll
        for (int mf = 0; mf < 2; mf++) {
            int m0 = mbase + mf * 16 + r;
            #pragma unroll
            for (int nt = 0; nt < 4; nt++) {
                int n0 = nt * 8 + t2;
                if (n0 < N_NODES)     atomicAdd(&dst[(size_t)n0 * E_DIM + m0],           acc[mf][nt][0] * hw);
                if (n0 + 1 < N_NODES) atomicAdd(&dst[(size_t)(n0 + 1) * E_DIM + m0],     acc[mf][nt][1] * hw);
                if (n0 < N_NODES)     atomicAdd(&dst[(size_t)n0 * E_DIM + m0 + 8],       acc[mf][nt][2] * hw);
                if (n0 + 1 < N_NODES) atomicAdd(&dst[(size_t)(n0 + 1) * E_DIM + m0 + 8], acc[mf][nt][3] * hw);
            }
        }
    }
}

// =====================================================================
// Scores (64-ch tiles, grid (20,4)) + last-block softmax + adjacency
// =====================================================================
__global__ __launch_bounds__(256)
void attn_scores(const float* __restrict__ gb, float* __restrict__ out)
{
    const int ct = blockIdx.x;   // 0..19
    const int h  = blockIdx.y;   // 0..3
    __shared__ float sq[64 * 29];
    __shared__ float sk[64 * 29];
    __shared__ int isLast;
    const int tid = threadIdx.x;

    const float4* qb = (const float4*)(g_qkvT + (size_t)(h * HD + ct * 64) * 28);
    const float4* kb = (const float4*)(g_qkvT + (size_t)(E_DIM + h * HD + ct * 64) * 28);
    for (int idx = tid; idx < 448; idx += 256) {   // 64*28/4
        int c = idx / 7, r4 = idx - c * 7;
        float4 q4 = qb[idx], k4 = kb[idx];
        int b = c * 29 + r4 * 4;
        sq[b] = q4.x; sq[b + 1] = q4.y; sq[b + 2] = q4.z; sq[b + 3] = q4.w;
        sk[b] = k4.x; sk[b + 1] = k4.y; sk[b + 2] = k4.z; sk[b + 3] = k4.w;
    }
    __syncthreads();

    for (int t = tid; t < 729; t += 256) {
        int i = t / 27, j = t - i * 27;
        float s0 = 0.0f, s1 = 0.0f;
        #pragma unroll
        for (int c = 0; c < 64; c += 2) {
            s0 += sq[c * 29 + i] * sk[c * 29 + j];
            s1 += sq[(c + 1) * 29 + i] * sk[(c + 1) * 29 + j];
        }
        atomicAdd(&g_scores[h * 729 + t], s0 + s1);
    }

    __threadfence();
    if (tid == 0) isLast = (atomicAdd(&g_cnt, 1) == 79);
    __syncthreads();
    if (!isLast) return;

    if (tid < 108) {   // softmax per (head, query)
        const int hh = tid / 27, i = tid - hh * 27;
        const float scale = rsqrtf((float)HD);
        const float* sc = g_scores + hh * 729 + i * 27;
        float mx = -1e30f;
        #pragma unroll
        for (int j = 0; j < 27; j++) mx = fmaxf(mx, sc[j] * scale);
        float e[27], sum = 0.0f;
        #pragma unroll
        for (int j = 0; j < 27; j++) { e[j] = expf(sc[j] * scale - mx); sum += e[j]; }
        const float inv = 1.0f / sum;
        float* at = g_attn + hh * 729 + i * 27;
        #pragma unroll
        for (int j = 0; j < 27; j++) at[j] = e[j] * inv;
    }
    for (int idx = tid; idx < 729; idx += 256) {   // causal adjacency
        int i = idx / 27, j = idx - i * 27;
        float v = 0.0f;
        if (i != j)
            v = 1.0f / (1.0f + expf(-(g_colrow[i] + g_colrow[27 + j] + gb[0])));
        out[N_NODES * E_DIM + idx] = v;
    }
}

// =====================================================================
// attn_out fused with GEMM2 fragment emission (no g_o round trip)
// grid (10,4): 128 channels = 8 k16 per block
// =====================================================================
__global__ __launch_bounds__(256)
void attn_out_frag()
{
    const int ct = blockIdx.x;
    const int h  = blockIdx.y;
    __shared__ float sv[128 * 29];
    __shared__ float sa[729];
    __shared__ float sto[128 * 28];   // o[c][i], stride 28
    const int tid = threadIdx.x;

    const float4* vb = (const float4*)(g_qkvT + (size_t)(2 * E_DIM + h * HD + ct * 128) * 28);
    for (int idx = tid; idx < 896; idx += 256) {   // 128*28/4
        int c = idx / 7, r4 = idx - c * 7;
        float4 v4 = vb[idx];
        int b = c * 29 + r4 * 4;
        sv[b] = v4.x; sv[b + 1] = v4.y; sv[b + 2] = v4.z; sv[b + 3] = v4.w;
    }
    for (int idx = tid; idx < 729; idx += 256) sa[idx] = g_attn[h * 729 + idx];
    __syncthreads();

    for (int f = tid; f < 27 * 128; f += 256) {
        int c = f & 127, i = f >> 7;
        float o = 0.0f;
        #pragma unroll
        for (int j = 0; j < 27; j++) o += sa[i * 27 + j] * sv[c * 29 + j];
        sto[c * 28 + i] = o;
    }
    __syncthreads();

    // fragment emission for this block's 8 k16 groups
    const int k16g0 = (h * HD + ct * 128) >> 4;
    const int lane = tid & 31;
    const int f    = tid >> 5;          // 0..7
    const int nt   = f >> 1, reg = f & 1;
    const int n    = nt * 8 + (lane >> 2);
    const int cb   = reg * 8 + 2 * (lane & 3);
    const bool ok  = (n < N_NODES);
    #pragma unroll
    for (int k16l = 0; k16l < 8; k16l++) {
        int c = k16l * 16 + cb;
        float f0 = ok ? sto[c * 28 + n]       : 0.0f;
        float f1 = ok ? sto[(c + 1) * 28 + n] : 0.0f;
        uint32_t hi, lo;
        split_pack(f0, f1, hi, lo);
        int idx = (k16g0 + k16l) * 256 + f * 32 + lane;
        g_bhi[idx] = hi;
        g_blo[idx] = lo;
    }
}

// =====================================================================
extern "C" void kernel_launch(void* const* d_in, const int* in_sizes, int n_in,
                              void* d_out, int out_size)
{
    const float* node = (const float*)d_in[0];
    const float* hist = (const float*)d_in[1];
    const float* gw   = (const float*)d_in[2];
    const float* gb   = (const float*)d_in[3];
    const float* inw  = (const float*)d_in[4];
    const float* inb  = (const float*)d_in[5];
    const float* outw = (const float*)d_in[6];
    const float* outb = (const float*)d_in[7];
    const int*   lh   = (const int*)d_in[8];
    float* out = (float*)d_out;

    const int init_elems = 15360 * 27 + 27 * 5120 + 4 * 729 + 1;
    const int init_blocks = (init_elems + 255) / 256;
    pre_kernel<<<134 + init_blocks, 256>>>(node, hist, gw, inb, outb, lh, out);

    // qkv += x @ in_proj_w^T : 120 M-tiles x 3 K-splits (107/107/106 k16)
    gemm_hmma<<<dim3(120, 3), 128>>>(inw, nullptr, 0, 107, lh);

    attn_scores<<<dim3(20, 4), 256>>>(gb, out);
    attn_out_frag<<<dim3(10, 4), 256>>>();

    // out += (o @ out_proj_w^T) * hw : 40 M-tiles x 10 K-splits (32 k16 each)
    gemm_hmma<<<dim3(40, 10), 128>>>(outw, out, 1, 32, lh);
}

// round 9
// speedup vs baseline: 1.4665x; 1.0479x over previous
#include <cuda_runtime.h>
#include <cstdint>

#define K_DIM   5120
#define E_DIM   5120
#define N_NODES 27
#define HD      1280

// ---- scratch (device globals; no allocations allowed) ----
__device__ float    g_qkvT[15360 * 28];    // qkv transposed [3E][28]
__device__ float    g_colrow[54];
__device__ float    g_scores[4 * 729];
__device__ float    g_attn[4 * 729];
__device__ int      g_cnt;
__device__ int      g_flag;
// B operand in MMA-fragment order: [k16 (320)][frag (8 = nt*2+reg)][lane (32)]
__device__ uint32_t g_bhi[320 * 256];
__device__ uint32_t g_blo[320 * 256];

static __device__ __forceinline__ float hw_from(const int* lh) {
    int iv = *lh;
    float f = (iv > 0 && iv < 100000000) ? (float)iv : __int_as_float(iv);
    return fminf(fmaxf(f * 0.001f, 0.1f), 1.0f);
}

// Split f32 pair -> bf16x2 hi (exact truncation) + bf16x2 lo (rounded remainder).
static __device__ __forceinline__ void split_pack(float f0, float f1,
                                                  uint32_t& hi, uint32_t& lo) {
    uint32_t u0 = __float_as_uint(f0), u1 = __float_as_uint(f1);
    asm("prmt.b32 %0, %1, %2, 0x7632;" : "=r"(hi) : "r"(u0), "r"(u1));
    float l0 = f0 - __uint_as_float(u0 & 0xFFFF0000u);
    float l1 = f1 - __uint_as_float(u1 & 0xFFFF0000u);
    asm("cvt.rn.bf16x2.f32 %0, %1, %2;" : "=r"(lo) : "f"(l1), "f"(l0));
}

#define MMA_BF16(d, a, b0, b1)                                                  \
    asm volatile(                                                               \
        "mma.sync.aligned.m16n8k16.row.col.f32.bf16.bf16.f32 "                  \
        "{%0,%1,%2,%3}, {%4,%5,%6,%7}, {%8,%9}, {%0,%1,%2,%3};"                 \
        : "+f"((d)[0]), "+f"((d)[1]), "+f"((d)[2]), "+f"((d)[3])                \
        : "r"((a)[0]), "r"((a)[1]), "r"((a)[2]), "r"((a)[3]),                   \
          "r"(b0), "r"(b1))

// =====================================================================
// Fragment prep for X (27 x 5120): b-frag for m16n8k16:
//   reg0 = X[n = nt*8 + lane>>2][k0, k0+1], reg1 = [k0+8, k0+9],
//   k0 = k16*16 + 2*(lane&3).  4 k16 per thread for ILP.
// =====================================================================
static __device__ __forceinline__ void prep_body(const float* __restrict__ src, int t4)
{
    int lane = t4 & 31;
    int f    = (t4 >> 5) & 7;
    int k16b = (t4 >> 8) * 4;
    int reg  = f & 1;
    int nt   = f >> 1;
    int n    = nt * 8 + (lane >> 2);
    const bool ok = (n < N_NODES);
    const float* row = src + (size_t)n * K_DIM;
    float f0[4], f1[4];
    #pragma unroll
    for (int u = 0; u < 4; u++) {
        int k0 = (k16b + u) * 16 + reg * 8 + 2 * (lane & 3);
        f0[u] = ok ? row[k0]     : 0.0f;
        f1[u] = ok ? row[k0 + 1] : 0.0f;
    }
    #pragma unroll
    for (int u = 0; u < 4; u++) {
        uint32_t hi, lo;
        split_pack(f0[u], f1[u], hi, lo);
        int idx = (k16b + u) * 256 + f * 32 + lane;
        g_bhi[idx] = hi;
        g_blo[idx] = lo;
    }
}

// =====================================================================
// pre: blocks [0,80) prep node frags | [80,134) granger dots | rest init
// =====================================================================
__global__ __launch_bounds__(256)
void pre_kernel(const float* __restrict__ node, const float* __restrict__ hist,
                const float* __restrict__ gw, const float* __restrict__ inb,
                const float* __restrict__ outb, const int* __restrict__ lh,
                float* __restrict__ out)
{
    const int bx = blockIdx.x;
    const int tid = threadIdx.x;

    if (bx < 80) { prep_body(node, bx * 256 + tid); return; }

    if (bx < 134) {   // granger dot b (0..53)
        const int b = bx - 80;
        const float* x  = (b < 27) ? node + (size_t)b * E_DIM : hist + (size_t)(b - 27) * E_DIM;
        const float* wv = (b < 27) ? gw + E_DIM : gw;
        float s = 0.0f;
        for (int k = tid; k < E_DIM; k += 256) s += x[k] * wv[k];
        __shared__ float sred[8];
        #pragma unroll
        for (int off = 16; off; off >>= 1) s += __shfl_xor_sync(0xffffffffu, s, off);
        if ((tid & 31) == 0) sred[tid >> 5] = s;
        __syncthreads();
        if (tid < 8) {
            s = sred[tid];
            #pragma unroll
            for (int off = 4; off; off >>= 1) s += __shfl_xor_sync(0x000000ffu, s, off);
            if (tid == 0) g_colrow[b] = s;
        }
        return;
    }

    int t = (bx - 134) * 256 + tid;
    if (t < 15360 * 27) {                       // qkvT bias seed
        int m = t / 27, n = t - m * 27;
        g_qkvT[m * 28 + n] = inb[m];
    } else if (t < 15360 * 27 + 27 * 5120) {    // out bias*hw seed
        int t2 = t - 15360 * 27;
        out[t2] = outb[t2 % 5120] * hw_from(lh);
    } else if (t < 15360 * 27 + 27 * 5120 + 4 * 729) {
        g_scores[t - (15360 * 27 + 27 * 5120)] = 0.0f;
    } else if (t == 15360 * 27 + 27 * 5120 + 4 * 729) {
        g_cnt = 0;
        g_flag = 0;
    }
}

// =====================================================================
// Barrier-free HMMA split-K GEMM, 64 rows/warp (4 m-frags):
//   D[m][n] = sum_k W[m][k] * X[n][k]
//   128 thr = 4 warps x 64 rows = 256 rows/CTA.
//   A: dist-2 reg prefetch (DRAM). B: dist-1 reg prefetch from L2 frags.
//   Compile-time buffer indices via template -> no local-memory demotion.
// =====================================================================
template<int BUF>
static __device__ __forceinline__ void gstep(
    int& i, int nk16, int k16_0, const float* __restrict__ wp, int lane,
    float2 (&Ast)[2][16], uint32_t (&Bh)[2][8], uint32_t (&Bl)[2][8],
    float (&acc)[4][4][4])
{
    constexpr int NBUF = BUF ^ 1;
    // B prefetch for i+1 (L2 hit, one full step of slack)
    if (i + 1 < nk16) {
        const int kb = (k16_0 + i + 1) * 256 + lane;
        #pragma unroll
        for (int f = 0; f < 8; f++) {
            Bh[NBUF][f] = g_bhi[kb + f * 32];
            Bl[NBUF][f] = g_blo[kb + f * 32];
        }
    }
    // convert staged A (waits on loads issued at i-2)
    uint32_t ahi[4][4], alo[4][4];
    #pragma unroll
    for (int q = 0; q < 16; q++)
        split_pack(Ast[BUF][q].x, Ast[BUF][q].y, ahi[q >> 2][q & 3], alo[q >> 2][q & 3]);
    // A prefetch for i+2 into freed buffer
    if (i + 2 < nk16) {
        #pragma unroll
        for (int mf = 0; mf < 4; mf++)
            #pragma unroll
            for (int kc = 0; kc < 2; kc++)
                #pragma unroll
                for (int rr = 0; rr < 2; rr++)
                    Ast[BUF][mf * 4 + kc * 2 + rr] =
                        *(const float2*)(wp + (size_t)(mf * 16 + rr * 8) * K_DIM
                                         + (size_t)(i + 2) * 16 + kc * 8);
    }
    #pragma unroll
    for (int mf = 0; mf < 4; mf++)
        #pragma unroll
        for (int nt = 0; nt < 4; nt++) {
            MMA_BF16(acc[mf][nt], ahi[mf], Bh[BUF][nt * 2], Bh[BUF][nt * 2 + 1]);
            MMA_BF16(acc[mf][nt], ahi[mf], Bl[BUF][nt * 2], Bl[BUF][nt * 2 + 1]);
            MMA_BF16(acc[mf][nt], alo[mf], Bh[BUF][nt * 2], Bh[BUF][nt * 2 + 1]);
        }
    i++;
}

__global__ __launch_bounds__(128, 2)
void gemm_hmma(const float* __restrict__ W, float* __restrict__ dst,
               int mode, int spl16, const int* __restrict__ lh)
{
    const int tid  = threadIdx.x;
    const int lane = tid & 31;
    const int wid  = tid >> 5;
    const int mbase = blockIdx.x * 256 + wid * 64;
    const int k16_0 = blockIdx.y * spl16;
    const int nk16  = min(spl16, 320 - k16_0);
    const int r  = lane >> 2;
    const int t2 = (lane & 3) * 2;

    const float* wp = W + (size_t)(mbase + r) * K_DIM + (size_t)k16_0 * 16 + t2;

    float acc[4][4][4];
    #pragma unroll
    for (int mf = 0; mf < 4; mf++)
        #pragma unroll
        for (int nt = 0; nt < 4; nt++)
            #pragma unroll
            for (int q = 0; q < 4; q++) acc[mf][nt][q] = 0.0f;

    float2   Ast[2][16];
    uint32_t Bh[2][8], Bl[2][8];

    // prologue: A(0)->buf0, A(1)->buf1, B(0)->buf0
    #pragma unroll
    for (int mf = 0; mf < 4; mf++)
        #pragma unroll
        for (int kc = 0; kc < 2; kc++)
            #pragma unroll
            for (int rr = 0; rr < 2; rr++)
                Ast[0][mf * 4 + kc * 2 + rr] =
                    *(const float2*)(wp + (size_t)(mf * 16 + rr * 8) * K_DIM + kc * 8);
    if (nk16 > 1) {
        #pragma unroll
        for (int mf = 0; mf < 4; mf++)
            #pragma unroll
            for (int kc = 0; kc < 2; kc++)
                #pragma unroll
                for (int rr = 0; rr < 2; rr++)
                    Ast[1][mf * 4 + kc * 2 + rr] =
                        *(const float2*)(wp + (size_t)(mf * 16 + rr * 8) * K_DIM + 16 + kc * 8);
    }
    {
        const int kb = k16_0 * 256 + lane;
        #pragma unroll
        for (int f = 0; f < 8; f++) {
            Bh[0][f] = g_bhi[kb + f * 32];
            Bl[0][f] = g_blo[kb + f * 32];
        }
    }

    int i = 0;
    while (true) {
        gstep<0>(i, nk16, k16_0, wp, lane, Ast, Bh, Bl, acc);
        if (i >= nk16) break;
        gstep<1>(i, nk16, k16_0, wp, lane, Ast, Bh, Bl, acc);
        if (i >= nk16) break;
    }

    // epilogue: d0=(m0,n0) d1=(m0,n0+1) d2=(m0+8,n0) d3=(m0+8,n0+1)
    if (mode == 0) {
        #pragma unroll
        for (int mf = 0; mf < 4; mf++) {
            int m0 = mbase + mf * 16 + r;
            #pragma unroll
            for (int nt = 0; nt < 4; nt++) {
                int n0 = nt * 8 + t2;
                if (n0 < N_NODES)     atomicAdd(&g_qkvT[m0 * 28 + n0],           acc[mf][nt][0]);
                if (n0 + 1 < N_NODES) atomicAdd(&g_qkvT[m0 * 28 + n0 + 1],       acc[mf][nt][1]);
                if (n0 < N_NODES)     atomicAdd(&g_qkvT[(m0 + 8) * 28 + n0],     acc[mf][nt][2]);
                if (n0 + 1 < N_NODES) atomicAdd(&g_qkvT[(m0 + 8) * 28 + n0 + 1], acc[mf][nt][3]);
            }
        }
    } else {
        const float hw = hw_from(lh);
        #pragma unroll
        for (int mf = 0; mf < 4; mf++) {
            int m0 = mbase + mf * 16 + r;
            #pragma unroll
            for (int nt = 0; nt < 4; nt++) {
                int n0 = nt * 8 + t2;
                if (n0 < N_NODES)     atomicAdd(&dst[(size_t)n0 * E_DIM + m0],           acc[mf][nt][0] * hw);
                if (n0 + 1 < N_NODES) atomicAdd(&dst[(size_t)(n0 + 1) * E_DIM + m0],     acc[mf][nt][1] * hw);
                if (n0 < N_NODES)     atomicAdd(&dst[(size_t)n0 * E_DIM + m0 + 8],       acc[mf][nt][2] * hw);
                if (n0 + 1 < N_NODES) atomicAdd(&dst[(size_t)(n0 + 1) * E_DIM + m0 + 8], acc[mf][nt][3] * hw);
            }
        }
    }
}

// =====================================================================
// Fused attention: scores partials -> counter -> last-block softmax+adj
// -> flag -> all blocks AV + GEMM2 fragment emission.
// grid (10,4): block handles 128 channels for scores AND AV.
// 40 blocks << 148 SMs -> all resident, spin-wait is safe.
// =====================================================================
__global__ __launch_bounds__(256)
void attn_fused(const float* __restrict__ gb, float* __restrict__ out)
{
    const int ct = blockIdx.x;   // 0..9
    const int h  = blockIdx.y;   // 0..3
    __shared__ float sA[128 * 29];   // q tile, then v tile
    __shared__ float sB[128 * 29];   // k tile, then o (stride 28)
    __shared__ float sa[729];
    const int tid = threadIdx.x;

    // load q,k tiles (128 ch x 28, float4)
    const float4* qb = (const float4*)(g_qkvT + (size_t)(h * HD + ct * 128) * 28);
    const float4* kb = (const float4*)(g_qkvT + (size_t)(E_DIM + h * HD + ct * 128) * 28);
    for (int idx = tid; idx < 896; idx += 256) {
        int c = idx / 7, r4 = idx - c * 7;
        float4 q4 = qb[idx], k4 = kb[idx];
        int b = c * 29 + r4 * 4;
        sA[b] = q4.x; sA[b + 1] = q4.y; sA[b + 2] = q4.z; sA[b + 3] = q4.w;
        sB[b] = k4.x; sB[b + 1] = k4.y; sB[b + 2] = k4.z; sB[b + 3] = k4.w;
    }
    __syncthreads();

    // score partials over this block's 128 channels
    for (int t = tid; t < 729; t += 256) {
        int i = t / 27, j = t - i * 27;
        float s0 = 0.0f, s1 = 0.0f;
        #pragma unroll
        for (int c = 0; c < 128; c += 2) {
            s0 += sA[c * 29 + i] * sB[c * 29 + j];
            s1 += sA[(c + 1) * 29 + i] * sB[(c + 1) * 29 + j];
        }
        atomicAdd(&g_scores[h * 729 + t], s0 + s1);
    }
    __threadfence();
    __syncthreads();

    __shared__ int isLast;
    if (tid == 0) isLast = (atomicAdd(&g_cnt, 1) == 39);
    __syncthreads();

    // overwrite sA with V tile while waiting (q/k no longer needed)
    const float4* vb = (const float4*)(g_qkvT + (size_t)(2 * E_DIM + h * HD + ct * 128) * 28);
    for (int idx = tid; idx < 896; idx += 256) {
        int c = idx / 7, r4 = idx - c * 7;
        float4 v4 = vb[idx];
        int b = c * 29 + r4 * 4;
        sA[b] = v4.x; sA[b + 1] = v4.y; sA[b + 2] = v4.z; sA[b + 3] = v4.w;
    }

    if (isLast) {
        if (tid < 108) {   // softmax per (head, query)
            const int hh = tid / 27, i = tid - hh * 27;
            const float scale = rsqrtf((float)HD);
            const float* sc = g_scores + hh * 729 + i * 27;
            float mx = -1e30f;
            #pragma unroll
            for (int j = 0; j < 27; j++) mx = fmaxf(mx, sc[j] * scale);
            float e[27], sum = 0.0f;
            #pragma unroll
            for (int j = 0; j < 27; j++) { e[j] = expf(sc[j] * scale - mx); sum += e[j]; }
            const float inv = 1.0f / sum;
            float* at = g_attn + hh * 729 + i * 27;
            #pragma unroll
            for (int j = 0; j < 27; j++) at[j] = e[j] * inv;
        }
        for (int idx = tid; idx < 729; idx += 256) {   // causal adjacency
            int i = idx / 27, j = idx - i * 27;
            float v = 0.0f;
            if (i != j)
                v = 1.0f / (1.0f + expf(-(g_colrow[i] + g_colrow[27 + j] + gb[0])));
            out[N_NODES * E_DIM + idx] = v;
        }
        __syncthreads();
        __threadfence();
        if (tid == 0) *(volatile int*)&g_flag = 1;
    }

    // spin until softmax published (all 40 blocks resident -> safe)
    if (tid == 0) { while (*(volatile int*)&g_flag == 0) { } }
    __syncthreads();
    __threadfence();

    for (int idx = tid; idx < 729; idx += 256) sa[idx] = g_attn[h * 729 + idx];
    __syncthreads();

    // AV into sB (o[c][i], stride 28)
    for (int f = tid; f < 27 * 128; f += 256) {
        int c = f & 127, i = f >> 7;
        float o = 0.0f;
        #pragma unroll
        for (int j = 0; j < 27; j++) o += sa[i * 27 + j] * sA[c * 29 + j];
        sB[c * 28 + i] = o;
    }
    __syncthreads();

    // GEMM2 fragment emission for this block's 8 k16 groups
    const int k16g0 = (h * HD + ct * 128) >> 4;
    const int lane = tid & 31;
    const int f    = tid >> 5;          // 0..7
    const int nt   = f >> 1, reg = f & 1;
    const int n    = nt * 8 + (lane >> 2);
    const int cb   = reg * 8 + 2 * (lane & 3);
    const bool ok  = (n < N_NODES);
    #pragma unroll
    for (int k16l = 0; k16l < 8; k16l++) {
        int c = k16l * 16 + cb;
        float f0 = ok ? sB[c * 28 + n]       : 0.0f;
        float f1 = ok ? sB[(c + 1) * 28 + n] : 0.0f;
        uint32_t hi, lo;
        split_pack(f0, f1, hi, lo);
        int idx = (k16g0 + k16l) * 256 + f * 32 + lane;
        g_bhi[idx] = hi;
        g_blo[idx] = lo;
    }
}

// =====================================================================
extern "C" void kernel_launch(void* const* d_in, const int* in_sizes, int n_in,
                              void* d_out, int out_size)
{
    const float* node = (const float*)d_in[0];
    const float* hist = (const float*)d_in[1];
    const float* gw   = (const float*)d_in[2];
    const float* gb   = (const float*)d_in[3];
    const float* inw  = (const float*)d_in[4];
    const float* inb  = (const float*)d_in[5];
    const float* outw = (const float*)d_in[6];
    const float* outb = (const float*)d_in[7];
    const int*   lh   = (const int*)d_in[8];
    float* out = (float*)d_out;

    const int init_elems = 15360 * 27 + 27 * 5120 + 4 * 729 + 1;
    const int init_blocks = (init_elems + 255) / 256;
    pre_kernel<<<134 + init_blocks, 256>>>(node, hist, gw, inb, outb, lh, out);

    // qkv += x @ in_proj_w^T : 60 M-tiles (256 rows) x 4 K-splits (80 k16)
    gemm_hmma<<<dim3(60, 4), 128>>>(inw, nullptr, 0, 80, lh);

    attn_fused<<<dim3(10, 4), 256>>>(gb, out);

    // out += (o @ out_proj_w^T) * hw : 20 M-tiles x 14 K-splits (23 k16)
    gemm_hmma<<<dim3(20, 14), 128>>>(outw, out, 1, 23, lh);
}